// round 1
// baseline (speedup 1.0000x reference)
#include <cuda_runtime.h>

// Problem constants (mirror the reference)
#define N_NEURONS 6
#define STEPS 10
#define SUBSTEPS 8
#define A_P 0.02f
#define B_P 0.2f
#define C_P (-65.0f)
#define D_P 8.0f
#define I_TONIC (-1.0f)
#define SYNTH 0.05f
#define SUPPR 0.1f
#define EMA_ALPHA 0.05f
#define RATE_DECAY 0.95f
#define PC_DT 0.1f

__device__ __forceinline__ float warp_sum(float x) {
    #pragma unroll
    for (int m = 16; m > 0; m >>= 1)
        x += __shfl_xor_sync(0xFFFFFFFFu, x, m);
    return x;
}

__global__ void spiking_pineal_kernel(
    const float* __restrict__ light_level,
    const float* __restrict__ retinal_luminance,
    const float* __restrict__ melatonin_raw,
    const float* __restrict__ mel_ema,
    const float* __restrict__ v_in,
    const float* __restrict__ u_in,
    const float* __restrict__ rate_in,
    const float* __restrict__ noise,      // [STEPS, N_NEURONS]
    const float* __restrict__ vs_in,      // [2,4]
    const float* __restrict__ va_in,      // [2,4]
    const float* __restrict__ prec_in,    // [2,4]
    float* __restrict__ out)              // [7]
{
    const int lane = threadIdx.x;

    // ---- scalar chemistry (computed redundantly in every lane) ----
    const float ll = *light_level;
    const float rl = *retinal_luminance;
    const float mraw = *melatonin_raw;
    const float mema = *mel_ema;

    const float light = fminf(1.0f, ll * 0.6f + rl * 0.4f);
    const float mel_sup = fmaxf(0.0f, mraw - SUPPR * light);
    const float mel_syn = fminf(1.0f, mraw + SYNTH * (1.0f - light));
    const float mel = (light > 0.3f) ? mel_sup : mel_syn;
    const float ema = mema + EMA_ALPHA * (mel - mema);

    // ---- Izhikevich: lanes 0..5, one neuron each ----
    float rate = 0.0f;
    if (lane < N_NEURONS) {
        // per-channel injected current
        float I;
        switch (lane) {
            case 0: I = light * 15.0f; break;
            case 1: I = light * 10.0f; break;
            case 2: I = (1.0f - light) * 8.0f; break;
            case 3: I = mel * 12.0f; break;
            case 4: I = mel * 8.0f; break;
            default: I = (1.0f - mel) * 6.0f; break;
        }

        // preload all 10 noise samples for this lane (burst: MLP=10)
        float nz[STEPS];
        #pragma unroll
        for (int s = 0; s < STEPS; s++)
            nz[s] = noise[s * N_NEURONS + lane];

        float v = v_in[lane];
        float u = u_in[lane];
        rate = rate_in[lane];

        #pragma unroll
        for (int s = 0; s < STEPS; s++) {
            const float I_in = I + I_TONIC + nz[s] * 0.3f;
            const float v2 = v + (0.04f * v * v + 5.0f * v + 140.0f - u + I_in);
            const float u2 = u + A_P * (B_P * v - u);
            const float spk = (v2 >= 30.0f) ? 1.0f : 0.0f;
            v = (spk > 0.0f) ? C_P : v2;
            u = u2 + D_P * spk;
            rate = RATE_DECAY * rate + (1.0f - RATE_DECAY) * spk;
        }
    }
    const float rate_sum = warp_sum(rate);

    // ---- predictive-coding column: lanes 0..7, one cell each ----
    float pe_abs = 0.0f, prec_new = 0.0f, fe_term = 0.0f;
    if (lane < 8) {
        const int ch = lane >> 2;                       // 0 or 1
        const float sens = (ch == 0) ? light : mel;
        const float pred = (ch == 0) ? light : ema;

        float vs = vs_in[lane];
        float va = va_in[lane];

        #pragma unroll
        for (int t = 0; t < SUBSTEPS; t++) {
            const float vs2 = vs + PC_DT * (-vs + sens + 0.5f * tanhf(va));
            const float va2 = va + PC_DT * (-va + pred);
            vs = vs2;
            va = va2;
        }

        const float pe = sens - tanhf(vs);
        const float prec = prec_in[lane];
        prec_new = prec + 0.1f * (1.0f / (1.0f + pe * pe) - prec);
        pe_abs = fabsf(pe);
        fe_term = prec_new * pe * pe;
    }

    const float pe_sum   = warp_sum(pe_abs);
    const float prec_sum = warp_sum(prec_new);
    const float fe_sum   = warp_sum(fe_term);

    if (lane == 0) {
        out[0] = light;
        out[1] = mel;
        out[2] = ema;
        out[3] = pe_sum / 8.0f;
        out[4] = prec_sum / 8.0f;
        out[5] = 0.5f * fe_sum;
        out[6] = rate_sum / (float)N_NEURONS;
    }
}

extern "C" void kernel_launch(void* const* d_in, const int* in_sizes, int n_in,
                              void* d_out, int out_size) {
    (void)in_sizes; (void)n_in; (void)out_size;
    spiking_pineal_kernel<<<1, 32>>>(
        (const float*)d_in[0],   // light_level
        (const float*)d_in[1],   // retinal_luminance
        (const float*)d_in[2],   // melatonin_raw
        (const float*)d_in[3],   // mel_ema
        (const float*)d_in[4],   // v
        (const float*)d_in[5],   // u
        (const float*)d_in[6],   // rate
        (const float*)d_in[7],   // noise
        (const float*)d_in[8],   // v_soma
        (const float*)d_in[9],   // v_apical
        (const float*)d_in[10],  // precision
        (float*)d_out);
}

// round 2
// speedup vs baseline: 1.0485x; 1.0485x over previous
#include <cuda_runtime.h>

#define N_NEURONS 6
#define STEPS 10
#define SUBSTEPS 8
#define A_P 0.02f
#define B_P 0.2f
#define C_P (-65.0f)
#define D_P 8.0f
#define I_TONIC (-1.0f)
#define SYNTH 0.05f
#define SUPPR 0.1f
#define EMA_ALPHA 0.05f
#define RATE_DECAY 0.95f
#define PC_DT 0.1f

// tanh via MUFU.EX2 + fast divide: err ~1e-6, no branches, short latency
__device__ __forceinline__ float ftanh(float x) {
    float e = __expf(2.0f * x);
    return 1.0f - __fdividef(2.0f, e + 1.0f);
}

// sum within groups of 8 lanes (values outside group contribute only to their own group)
__device__ __forceinline__ float sum8(float x) {
    x += __shfl_xor_sync(0xFFFFFFFFu, x, 4);
    x += __shfl_xor_sync(0xFFFFFFFFu, x, 2);
    x += __shfl_xor_sync(0xFFFFFFFFu, x, 1);
    return x;
}

__global__ void __launch_bounds__(32, 1) spiking_pineal_kernel(
    const float* __restrict__ light_level,
    const float* __restrict__ retinal_luminance,
    const float* __restrict__ melatonin_raw,
    const float* __restrict__ mel_ema,
    const float* __restrict__ v_in,
    const float* __restrict__ u_in,
    const float* __restrict__ rate_in,
    const float* __restrict__ noise,      // [STEPS, N_NEURONS]
    const float* __restrict__ vs_in,      // [2,4]
    const float* __restrict__ va_in,      // [2,4]
    const float* __restrict__ prec_in,    // [2,4]
    float* __restrict__ out)              // [7]
{
    const int lane = threadIdx.x & 31;
    const int li = lane < N_NEURONS ? lane : N_NEURONS - 1;  // clamped neuron idx
    const int pi = lane < 8 ? lane : 7;                      // clamped PC idx

    // ---- issue ALL loads up front (independent, MLP) ----
    const float ll   = *light_level;
    const float rl   = *retinal_luminance;
    const float mraw = *melatonin_raw;
    const float mema = *mel_ema;

    float v    = v_in[li];
    float u    = u_in[li];
    float rate = rate_in[li];

    float nz[STEPS];
    #pragma unroll
    for (int s = 0; s < STEPS; s++)
        nz[s] = noise[s * N_NEURONS + li];

    float vs0  = vs_in[pi];
    float va0  = va_in[pi];
    float prec = prec_in[pi];

    // ---- scalar chemistry ----
    const float light   = fminf(1.0f, ll * 0.6f + rl * 0.4f);
    const float mel_sup = fmaxf(0.0f, mraw - SUPPR * light);
    const float mel_syn = fminf(1.0f, mraw + SYNTH * (1.0f - light));
    const float mel     = (light > 0.3f) ? mel_sup : mel_syn;
    const float ema     = mema + EMA_ALPHA * (mel - mema);

    // per-neuron injected current (selects, branchless)
    float I =
        (lane == 0) ? light * 15.0f :
        (lane == 1) ? light * 10.0f :
        (lane == 2) ? (1.0f - light) * 8.0f :
        (lane == 3) ? mel * 12.0f :
        (lane == 4) ? mel * 8.0f :
                      (1.0f - mel) * 6.0f;
    const float Ibase = I + I_TONIC;

    // ---- Izhikevich, 10 serial steps (straight-line, no lane branches) ----
    #pragma unroll
    for (int s = 0; s < STEPS; s++) {
        const float I_in = fmaf(nz[s], 0.3f, Ibase);
        // v2 = v + 0.04v^2 + 5v + 140 - u + I_in  == fma(v, fma(0.04,v,6), 140-u+I_in)
        const float v2 = fmaf(v, fmaf(0.04f, v, 6.0f), 140.0f - u + I_in);
        const float u2 = fmaf(A_P, fmaf(B_P, v, -u), u);
        const float spk = (v2 >= 30.0f) ? 1.0f : 0.0f;
        v = (v2 >= 30.0f) ? C_P : v2;
        u = fmaf(D_P, spk, u2);
        rate = fmaf(RATE_DECAY, rate, (1.0f - RATE_DECAY) * spk);
    }

    // ---- predictive-coding column, closed form ----
    // va_t = pred + 0.9^t * (va0 - pred)      (va recurrence is linear)
    // vs_8 = 0.9^8*vs0 + 0.1*sens*S + 0.05 * sum_t 0.9^(7-t) * tanh(va_t)
    const int ch = (pi >> 2);
    const float sens = (ch == 0) ? light : mel;
    const float pred = (ch == 0) ? light : ema;

    const float p9[9] = {1.0f, 0.9f, 0.81f, 0.729f, 0.6561f, 0.59049f,
                         0.531441f, 0.4782969f, 0.43046721f};
    const float dva = va0 - pred;

    // 8 independent tanh evaluations (MUFU pipelined)
    float th[SUBSTEPS];
    #pragma unroll
    for (int t = 0; t < SUBSTEPS; t++)
        th[t] = ftanh(fmaf(p9[t], dva, pred));

    // weighted sum: sum_t 0.9^(7-t) * th[t]  (tree-friendly)
    float wsum = 0.0f;
    #pragma unroll
    for (int t = 0; t < SUBSTEPS; t++)
        wsum = fmaf(p9[7 - t], th[t], wsum);

    const float S8 = (1.0f - 0.43046721f) / 0.1f;  // sum_{t=0..7} 0.9^t
    const float vs = fmaf(0.43046721f, vs0,
                     fmaf(0.1f * S8, sens, 0.05f * wsum));

    const float pe = sens - ftanh(vs);
    const float pe2 = pe * pe;
    const float prec_new = fmaf(0.1f, __fdividef(1.0f, 1.0f + pe2) - prec, prec);

    // ---- reductions (groups of 8; zero contributions outside valid lanes) ----
    const float r_c  = (lane < N_NEURONS) ? rate : 0.0f;
    const float pe_c = (lane < 8) ? fabsf(pe) : 0.0f;
    const float pr_c = (lane < 8) ? prec_new : 0.0f;
    const float fe_c = (lane < 8) ? prec_new * pe2 : 0.0f;

    const float rate_sum = sum8(r_c);
    const float pe_sum   = sum8(pe_c);
    const float prec_sum = sum8(pr_c);
    const float fe_sum   = sum8(fe_c);

    if (lane == 0) {
        out[0] = light;
        out[1] = mel;
        out[2] = ema;
        out[3] = pe_sum * 0.125f;
        out[4] = prec_sum * 0.125f;
        out[5] = 0.5f * fe_sum;
        out[6] = rate_sum * (1.0f / (float)N_NEURONS);
    }
}

extern "C" void kernel_launch(void* const* d_in, const int* in_sizes, int n_in,
                              void* d_out, int out_size) {
    (void)in_sizes; (void)n_in; (void)out_size;
    spiking_pineal_kernel<<<1, 32>>>(
        (const float*)d_in[0],   // light_level
        (const float*)d_in[1],   // retinal_luminance
        (const float*)d_in[2],   // melatonin_raw
        (const float*)d_in[3],   // mel_ema
        (const float*)d_in[4],   // v
        (const float*)d_in[5],   // u
        (const float*)d_in[6],   // rate
        (const float*)d_in[7],   // noise
        (const float*)d_in[8],   // v_soma
        (const float*)d_in[9],   // v_apical
        (const float*)d_in[10],  // precision
        (float*)d_out);
}